// round 4
// baseline (speedup 1.0000x reference)
#include <cuda_runtime.h>
#include <math.h>

#define DD 128
#define MAXN 100000
#define MAXE 1600000
#define NPARTMAX 512
#define PADB 68   // sB row stride in floats

// ---------------- scratch (device globals; referenced directly by kernels) ----------------
__device__ int   g_is64;
__device__ int   g_src [MAXE];
__device__ int   g_dst [MAXE];
__device__ float g_dinv[MAXN];
__device__ int   g_cnt [MAXN];
__device__ int   g_off [MAXN];
__device__ int   g_cur [MAXN];
__device__ int   g_csr [MAXE];
__device__ int   g_part[NPARTMAX];
__device__ float g_hw [ (size_t)MAXN * DD ];
__device__ float g_h0 [ (size_t)MAXN * DD ];
__device__ float g_h1 [ (size_t)MAXN * DD ];
__device__ float g_h2 [ (size_t)MAXN * DD ];

__device__ __forceinline__ const float* sel_in(int sel, const float* x) {
    return sel == 0 ? x : (sel == 1 ? g_h0 : (sel == 2 ? g_h1 : g_h2));
}
__device__ __forceinline__ float* sel_out(int sel) {
    return sel == 0 ? g_h0 : (sel == 1 ? g_h1 : g_h2);
}

// ---------------- edge dtype detect + normalize ----------------
// Reads only the first 64 int64 slots (= first 512 bytes), safe under both layouts.
__global__ void detect_kernel(const void* ei, int n) {
    if (threadIdx.x == 0 && blockIdx.x == 0) {
        const long long* e64 = (const long long*)ei;
        int is64 = 1;
        for (int i = 0; i < 64; i++) {
            long long v = e64[i];
            if (v < 0 || v >= (long long)n) { is64 = 0; break; }
        }
        g_is64 = is64;
    }
}

// Normalize to int32 src/dst with bounds clamping (never trap downstream).
__global__ void convert_kernel(const void* ei, int ne, int n) {
    int e = blockIdx.x * blockDim.x + threadIdx.x;
    if (e >= ne) return;
    int s, d;
    if (g_is64) {
        const long long* p = (const long long*)ei;
        s = (int)p[e];
        d = (int)p[(size_t)ne + e];
    } else {
        const int* p = (const int*)ei;
        s = p[e];
        d = p[(size_t)ne + e];
    }
    if ((unsigned)s >= (unsigned)n) s = 0;
    if ((unsigned)d >= (unsigned)n) d = 0;
    g_src[e] = s;
    g_dst[e] = d;
}

// ---------------- CSR build ----------------
__global__ void zero_kernel(int n) {
    int i = blockIdx.x * blockDim.x + threadIdx.x;
    if (i < n) { g_cnt[i] = 0; g_cur[i] = 0; }
}

__global__ void hist_kernel(int ne) {
    int e = blockIdx.x * blockDim.x + threadIdx.x;
    if (e < ne) atomicAdd(&g_cnt[g_dst[e]], 1);
}

__global__ void scan1_kernel(int n) {
    __shared__ int sh[256];
    int tid = threadIdx.x;
    int i = blockIdx.x * 256 + tid;
    int v = (i < n) ? g_cnt[i] : 0;
    sh[tid] = v;
    __syncthreads();
#pragma unroll
    for (int d = 1; d < 256; d <<= 1) {
        int t = (tid >= d) ? sh[tid - d] : 0;
        __syncthreads();
        sh[tid] += t;
        __syncthreads();
    }
    if (i < n) g_off[i] = sh[tid] - v;
    if (tid == 255) g_part[blockIdx.x] = sh[255];
}

__global__ void scan2_kernel(int npart) {
    __shared__ int sh[NPARTMAX];
    int tid = threadIdx.x;
    int v = (tid < npart) ? g_part[tid] : 0;
    sh[tid] = v;
    __syncthreads();
#pragma unroll
    for (int d = 1; d < NPARTMAX; d <<= 1) {
        int t = (tid >= d) ? sh[tid - d] : 0;
        __syncthreads();
        sh[tid] += t;
        __syncthreads();
    }
    if (tid < npart) g_part[tid] = sh[tid] - v;
}

__global__ void scan3_kernel(int n) {
    int i = blockIdx.x * blockDim.x + threadIdx.x;
    if (i < n) {
        g_off[i] += g_part[i >> 8];
        g_dinv[i] = rsqrtf((float)(g_cnt[i] + 1));
    }
}

__global__ void fill_kernel(int ne) {
    int e = blockIdx.x * blockDim.x + threadIdx.x;
    if (e < ne) {
        int d = g_dst[e];
        int p = g_off[d] + atomicAdd(&g_cur[d], 1);
        g_csr[p] = g_src[e];
    }
}

// ---------------- conv GEMM: g_hw = (hin @ W_l^T) * dinv[row] ----------------
__global__ void gemm_conv_kernel(const float* __restrict__ x,
                                 const float* __restrict__ conv_w,
                                 int layer, int n)
{
    __shared__ float sA[64 * 64];      // [row][k]
    __shared__ float sB[64 * PADB];    // [col][k] padded

    const float* A = sel_in(layer, x);
    const float* W = conv_w + (size_t)layer * DD * DD;

    int row0 = blockIdx.x * 64;
    int col0 = blockIdx.y * 64;
    int t  = threadIdx.x;
    int tx = t & 15;
    int ty = t >> 4;

    float acc[4][4];
#pragma unroll
    for (int i = 0; i < 4; i++)
#pragma unroll
        for (int j = 0; j < 4; j++) acc[i][j] = 0.f;

    for (int kh = 0; kh < 2; kh++) {
        for (int idx = t; idx < 4096; idx += 256) {
            int r = idx >> 6, k = idx & 63;
            int gr = row0 + r;
            sA[r * 64 + k] = (gr < n) ? A[(size_t)gr * DD + kh * 64 + k] : 0.f;
        }
        for (int idx = t; idx < 4096; idx += 256) {
            int c = idx >> 6, k = idx & 63;
            sB[c * PADB + k] = W[(size_t)(col0 + c) * DD + kh * 64 + k];
        }
        __syncthreads();

#pragma unroll
        for (int kk = 0; kk < 16; kk++) {
            float4 a4[4], b4[4];
#pragma unroll
            for (int i = 0; i < 4; i++)
                a4[i] = *(const float4*)&sA[(ty * 4 + i) * 64 + kk * 4];
#pragma unroll
            for (int j = 0; j < 4; j++)
                b4[j] = *(const float4*)&sB[(tx * 4 + j) * PADB + kk * 4];
#pragma unroll
            for (int i = 0; i < 4; i++)
#pragma unroll
                for (int j = 0; j < 4; j++) {
                    acc[i][j] = fmaf(a4[i].x, b4[j].x, acc[i][j]);
                    acc[i][j] = fmaf(a4[i].y, b4[j].y, acc[i][j]);
                    acc[i][j] = fmaf(a4[i].z, b4[j].z, acc[i][j]);
                    acc[i][j] = fmaf(a4[i].w, b4[j].w, acc[i][j]);
                }
        }
        __syncthreads();
    }

#pragma unroll
    for (int i = 0; i < 4; i++) {
        int gr = row0 + ty * 4 + i;
        if (gr < n) {
            float dv = g_dinv[gr];
            float4 v = make_float4(acc[i][0] * dv, acc[i][1] * dv,
                                   acc[i][2] * dv, acc[i][3] * dv);
            *(float4*)&g_hw[(size_t)gr * DD + col0 + tx * 4] = v;
        }
    }
}

// ------- fused aggregate + bias + ELU + residual: one warp per dst node -------
__global__ void aggregate_kernel(const float* __restrict__ x,
                                 const float* __restrict__ conv_b,
                                 int layer, int n)
{
    int w = (blockIdx.x * blockDim.x + threadIdx.x) >> 5;
    if (w >= n) return;
    int lane = threadIdx.x & 31;

    const float* hin = sel_in(layer, x);
    float* hout = sel_out(layer);
    const float* b = conv_b + (size_t)layer * DD;
    const float4* hw4 = (const float4*)g_hw;

    float4 a0 = hw4[(size_t)w * 32 + lane];   // self-loop (pre-scaled by dinv[w])
    float4 a1 = make_float4(0.f, 0.f, 0.f, 0.f);

    int j   = g_off[w];
    int end = j + g_cnt[w];
    for (; j + 2 <= end; j += 2) {
        int s0 = g_csr[j], s1 = g_csr[j + 1];
        float4 v0 = hw4[(size_t)s0 * 32 + lane];
        float4 v1 = hw4[(size_t)s1 * 32 + lane];
        a0.x += v0.x; a0.y += v0.y; a0.z += v0.z; a0.w += v0.w;
        a1.x += v1.x; a1.y += v1.y; a1.z += v1.z; a1.w += v1.w;
    }
    if (j < end) {
        int s0 = g_csr[j];
        float4 v0 = hw4[(size_t)s0 * 32 + lane];
        a0.x += v0.x; a0.y += v0.y; a0.z += v0.z; a0.w += v0.w;
    }

    float dv = g_dinv[w];
    float4 bb = ((const float4*)b)[lane];
    float4 hi = ((const float4*)hin)[(size_t)w * 32 + lane];
    float4 o;
    float x0 = (a0.x + a1.x) * dv + bb.x; o.x = (x0 > 0.f ? x0 : expm1f(x0)) + hi.x;
    float x1 = (a0.y + a1.y) * dv + bb.y; o.y = (x1 > 0.f ? x1 : expm1f(x1)) + hi.y;
    float x2 = (a0.z + a1.z) * dv + bb.z; o.z = (x2 > 0.f ? x2 : expm1f(x2)) + hi.z;
    float x3 = (a0.w + a1.w) * dv + bb.w; o.w = (x3 > 0.f ? x3 : expm1f(x3)) + hi.w;
    ((float4*)hout)[(size_t)w * 32 + lane] = o;
}

// ---------------- final linear: out = concat(x,h0,h1,h2) @ lin_w^T + lin_b -------------
__global__ void gemm_final_kernel(const float* __restrict__ x,
                                  const float* __restrict__ lw,   // [128, 512]
                                  const float* __restrict__ lb,   // [128]
                                  float* __restrict__ out, int n)
{
    __shared__ float sA[64 * 64];
    __shared__ float sB[64 * PADB];

    int row0 = blockIdx.x * 64;
    int col0 = blockIdx.y * 64;
    int t  = threadIdx.x;
    int tx = t & 15;
    int ty = t >> 4;

    float acc[4][4];
#pragma unroll
    for (int i = 0; i < 4; i++)
#pragma unroll
        for (int j = 0; j < 4; j++) acc[i][j] = 0.f;

    for (int ch = 0; ch < 4; ch++) {
        const float* A = sel_in(ch, x);
        for (int kh = 0; kh < 2; kh++) {
            for (int idx = t; idx < 4096; idx += 256) {
                int r = idx >> 6, k = idx & 63;
                int gr = row0 + r;
                sA[r * 64 + k] = (gr < n) ? A[(size_t)gr * DD + kh * 64 + k] : 0.f;
            }
            for (int idx = t; idx < 4096; idx += 256) {
                int c = idx >> 6, k = idx & 63;
                sB[c * PADB + k] = lw[(size_t)(col0 + c) * 512 + ch * DD + kh * 64 + k];
            }
            __syncthreads();

#pragma unroll
            for (int kk = 0; kk < 16; kk++) {
                float4 a4[4], b4[4];
#pragma unroll
                for (int i = 0; i < 4; i++)
                    a4[i] = *(const float4*)&sA[(ty * 4 + i) * 64 + kk * 4];
#pragma unroll
                for (int j = 0; j < 4; j++)
                    b4[j] = *(const float4*)&sB[(tx * 4 + j) * PADB + kk * 4];
#pragma unroll
                for (int i = 0; i < 4; i++)
#pragma unroll
                    for (int j = 0; j < 4; j++) {
                        acc[i][j] = fmaf(a4[i].x, b4[j].x, acc[i][j]);
                        acc[i][j] = fmaf(a4[i].y, b4[j].y, acc[i][j]);
                        acc[i][j] = fmaf(a4[i].z, b4[j].z, acc[i][j]);
                        acc[i][j] = fmaf(a4[i].w, b4[j].w, acc[i][j]);
                    }
            }
            __syncthreads();
        }
    }

#pragma unroll
    for (int i = 0; i < 4; i++) {
        int gr = row0 + ty * 4 + i;
        if (gr < n) {
            int c = col0 + tx * 4;
            float4 bb = *(const float4*)&lb[c];
            float4 v = make_float4(acc[i][0] + bb.x, acc[i][1] + bb.y,
                                   acc[i][2] + bb.z, acc[i][3] + bb.w);
            *(float4*)&out[(size_t)gr * DD + c] = v;
        }
    }
}

// ---------------- launch ----------------
extern "C" void kernel_launch(void* const* d_in, const int* in_sizes, int n_in,
                              void* d_out, int out_size)
{
    const float* x      = (const float*)d_in[0];
    const void*  ei     = d_in[1];                     // int32 or int64, detected on device
    const float* conv_w = (const float*)d_in[2];       // [3,128,128]
    const float* conv_b = (const float*)d_in[3];       // [3,128]
    const float* lin_w  = (const float*)d_in[4];       // [128,512]
    const float* lin_b  = (const float*)d_in[5];       // [128]
    float*       out    = (float*)d_out;

    int n = in_sizes[0] / DD;       // 100000
    int e = in_sizes[1] / 2;        // 1600000 (element count is 2E for both dtypes)

    int nb_n  = (n + 255) / 256;
    int nb_e  = (e + 255) / 256;
    int npart = (n + 255) / 256;    // 391 <= NPARTMAX

    detect_kernel <<<1, 32>>>(ei, n);
    convert_kernel<<<nb_e, 256>>>(ei, e, n);
    zero_kernel   <<<nb_n, 256>>>(n);
    hist_kernel   <<<nb_e, 256>>>(e);
    scan1_kernel  <<<npart, 256>>>(n);
    scan2_kernel  <<<1, NPARTMAX>>>(npart);
    scan3_kernel  <<<nb_n, 256>>>(n);
    fill_kernel   <<<nb_e, 256>>>(e);

    dim3 ggrid((n + 63) / 64, 2);
    int agg_blocks = (n * 32 + 255) / 256;

    for (int l = 0; l < 3; l++) {
        gemm_conv_kernel<<<ggrid, 256>>>(x, conv_w, l, n);
        aggregate_kernel<<<agg_blocks, 256>>>(x, conv_b, l, n);
    }

    gemm_final_kernel<<<ggrid, 256>>>(x, lin_w, lin_b, out, n);
}

// round 5
// speedup vs baseline: 1.9732x; 1.9732x over previous
#include <cuda_runtime.h>
#include <cuda_bf16.h>
#include <math.h>

#define DD 128
#define MAXN 100000
#define MAXE 1600000
#define NPARTMAX 512

// ---------------- scratch (device globals) ----------------
__device__ int   g_is64;
__device__ int   g_src [MAXE];
__device__ int   g_dst [MAXE];
__device__ float g_dinv[MAXN];
__device__ int   g_cnt [MAXN];
__device__ int   g_off [MAXN];
__device__ int   g_cur [MAXN];
__device__ int   g_csr [MAXE];
__device__ int   g_part[NPARTMAX];
__device__ float g_hw [ (size_t)MAXN * DD ];
__device__ float g_h0 [ (size_t)MAXN * DD ];
__device__ float g_h1 [ (size_t)MAXN * DD ];
__device__ float g_h2 [ (size_t)MAXN * DD ];

__device__ __forceinline__ const float* sel_in(int sel, const float* x) {
    return sel == 0 ? x : (sel == 1 ? g_h0 : (sel == 2 ? g_h1 : g_h2));
}
__device__ __forceinline__ float* sel_out(int sel) {
    return sel == 0 ? g_h0 : (sel == 1 ? g_h1 : g_h2);
}

// ---------------- edge dtype detect + normalize (+histogram fused) ----------------
__global__ void detect_kernel(const void* ei, int n) {
    if (threadIdx.x == 0 && blockIdx.x == 0) {
        const long long* e64 = (const long long*)ei;
        int is64 = 1;
        for (int i = 0; i < 64; i++) {
            long long v = e64[i];
            if (v < 0 || v >= (long long)n) { is64 = 0; break; }
        }
        g_is64 = is64;
    }
}

__global__ void zero_kernel(int n) {
    int i = blockIdx.x * blockDim.x + threadIdx.x;
    if (i < n) { g_cnt[i] = 0; g_cur[i] = 0; }
}

__global__ void convert_hist_kernel(const void* ei, int ne, int n) {
    int e = blockIdx.x * blockDim.x + threadIdx.x;
    if (e >= ne) return;
    int s, d;
    if (g_is64) {
        const long long* p = (const long long*)ei;
        s = (int)p[e];
        d = (int)p[(size_t)ne + e];
    } else {
        const int* p = (const int*)ei;
        s = p[e];
        d = p[(size_t)ne + e];
    }
    if ((unsigned)s >= (unsigned)n) s = 0;
    if ((unsigned)d >= (unsigned)n) d = 0;
    g_src[e] = s;
    g_dst[e] = d;
    atomicAdd(&g_cnt[d], 1);
}

// ---------------- CSR scan/fill ----------------
__global__ void scan1_kernel(int n) {
    __shared__ int sh[256];
    int tid = threadIdx.x;
    int i = blockIdx.x * 256 + tid;
    int v = (i < n) ? g_cnt[i] : 0;
    sh[tid] = v;
    __syncthreads();
#pragma unroll
    for (int d = 1; d < 256; d <<= 1) {
        int t = (tid >= d) ? sh[tid - d] : 0;
        __syncthreads();
        sh[tid] += t;
        __syncthreads();
    }
    if (i < n) g_off[i] = sh[tid] - v;
    if (tid == 255) g_part[blockIdx.x] = sh[255];
}

__global__ void scan2_kernel(int npart) {
    __shared__ int sh[NPARTMAX];
    int tid = threadIdx.x;
    int v = (tid < npart) ? g_part[tid] : 0;
    sh[tid] = v;
    __syncthreads();
#pragma unroll
    for (int d = 1; d < NPARTMAX; d <<= 1) {
        int t = (tid >= d) ? sh[tid - d] : 0;
        __syncthreads();
        sh[tid] += t;
        __syncthreads();
    }
    if (tid < npart) g_part[tid] = sh[tid] - v;
}

__global__ void scan3_kernel(int n) {
    int i = blockIdx.x * blockDim.x + threadIdx.x;
    if (i < n) {
        g_off[i] += g_part[i >> 8];
        g_dinv[i] = rsqrtf((float)(g_cnt[i] + 1));
    }
}

__global__ void fill_kernel(int ne) {
    int e = blockIdx.x * blockDim.x + threadIdx.x;
    if (e < ne) {
        int d = g_dst[e];
        int p = g_off[d] + atomicAdd(&g_cur[d], 1);
        g_csr[p] = g_src[e];
    }
}

// ---------------- bf16 hi/lo helpers ----------------
__device__ __forceinline__ uint2 cvt_pair(float a, float b) {
    __nv_bfloat16 ha = __float2bfloat16_rn(a);
    __nv_bfloat16 hb = __float2bfloat16_rn(b);
    float ra = a - __bfloat162float(ha);
    float rb = b - __bfloat162float(hb);
    __nv_bfloat162 hp = __halves2bfloat162(ha, hb);
    __nv_bfloat162 lp = __floats2bfloat162_rn(ra, rb);
    uint2 u;
    u.x = *(const unsigned int*)&hp;
    u.y = *(const unsigned int*)&lp;
    return u;
}

__device__ __forceinline__ void mma16816(float* d, const unsigned* a, const unsigned* b) {
    asm volatile(
        "mma.sync.aligned.m16n8k16.row.col.f32.bf16.bf16.f32 "
        "{%0,%1,%2,%3}, {%4,%5,%6,%7}, {%8,%9}, {%0,%1,%2,%3};\n"
        : "+f"(d[0]), "+f"(d[1]), "+f"(d[2]), "+f"(d[3])
        : "r"(a[0]), "r"(a[1]), "r"(a[2]), "r"(a[3]), "r"(b[0]), "r"(b[1]));
}

// ============== tensor-core GEMM (bf16x3): C[128rows x 128cols] per block ==============
// Computes C = A @ W^T with A[n,K], W[128,K] row-major, K processed in chunks of 32.
// mode 0: epilogue C *= dinv[row] -> g_hw     (conv layer)
// mode 1: epilogue C += lin_b     -> out      (final layer, 4 sources x 128 K each)
__global__ __launch_bounds__(256) void gemm_tc_kernel(
    const float* __restrict__ x,
    const float* __restrict__ wptr,   // conv: conv_w + layer*128*128 ; final: lin_w [128,512]
    const float* __restrict__ lb,     // final bias (mode 1)
    float* __restrict__ outp,         // final out (mode 1)
    int layer, int mode, int n)
{
    __shared__ uint2 sA[128 * 17];    // [row][kpair 0..15], pad 17
    __shared__ uint2 sW[128 * 17];    // [col][kpair]

    int row0 = blockIdx.x * 128;
    int t    = threadIdx.x;
    int warp = t >> 5;
    int lane = t & 31;
    int g    = lane >> 2;     // group row
    int t4   = lane & 3;
    int warp_m = warp & 3;    // 4 row groups of 32
    int warp_n = warp >> 2;   // 2 col groups of 64

    float acc[2][8][4];
#pragma unroll
    for (int a = 0; a < 2; a++)
#pragma unroll
        for (int b = 0; b < 8; b++)
#pragma unroll
            for (int c = 0; c < 4; c++) acc[a][b][c] = 0.f;

    int nsrc = (mode == 0) ? 1 : 4;
    int wstride = (mode == 0) ? DD : 512;

    for (int s = 0; s < nsrc; s++) {
        const float* A = (mode == 0) ? sel_in(layer, x) : sel_in(s, x);
        int kbase_src = (mode == 0) ? 0 : s * DD;

        for (int kc = 0; kc < 4; kc++) {
            int kb = kc * 32;
            // load + convert A chunk: 128 rows x 32 floats
            for (int idx = t; idx < 1024; idx += 256) {
                int r = idx >> 3, q = idx & 7;
                int gr = row0 + r;
                float4 f = make_float4(0.f, 0.f, 0.f, 0.f);
                if (gr < n) f = *(const float4*)&A[(size_t)gr * DD + kb + q * 4];
                sA[r * 17 + q * 2]     = cvt_pair(f.x, f.y);
                sA[r * 17 + q * 2 + 1] = cvt_pair(f.z, f.w);
            }
            // load + convert W chunk: 128 cols x 32 floats
            for (int idx = t; idx < 1024; idx += 256) {
                int c = idx >> 3, q = idx & 7;
                float4 f = *(const float4*)&wptr[(size_t)c * wstride + kbase_src + kb + q * 4];
                sW[c * 17 + q * 2]     = cvt_pair(f.x, f.y);
                sW[c * 17 + q * 2 + 1] = cvt_pair(f.z, f.w);
            }
            __syncthreads();

#pragma unroll
            for (int kk = 0; kk < 2; kk++) {
                int pb = kk * 8;
                unsigned ahi[2][4], alo[2][4];
#pragma unroll
                for (int mt = 0; mt < 2; mt++) {
                    int r0 = warp_m * 32 + mt * 16 + g;
                    uint2 u0 = sA[r0 * 17 + pb + t4];
                    uint2 u1 = sA[(r0 + 8) * 17 + pb + t4];
                    uint2 u2 = sA[r0 * 17 + pb + t4 + 4];
                    uint2 u3 = sA[(r0 + 8) * 17 + pb + t4 + 4];
                    ahi[mt][0] = u0.x; ahi[mt][1] = u1.x; ahi[mt][2] = u2.x; ahi[mt][3] = u3.x;
                    alo[mt][0] = u0.y; alo[mt][1] = u1.y; alo[mt][2] = u2.y; alo[mt][3] = u3.y;
                }
#pragma unroll
                for (int nh = 0; nh < 2; nh++) {
                    unsigned bhi[4][2], blo[4][2];
#pragma unroll
                    for (int j = 0; j < 4; j++) {
                        int c = warp_n * 64 + (nh * 4 + j) * 8 + g;
                        uint2 v0 = sW[c * 17 + pb + t4];
                        uint2 v1 = sW[c * 17 + pb + t4 + 4];
                        bhi[j][0] = v0.x; bhi[j][1] = v1.x;
                        blo[j][0] = v0.y; blo[j][1] = v1.y;
                    }
#pragma unroll
                    for (int mt = 0; mt < 2; mt++)
#pragma unroll
                        for (int j = 0; j < 4; j++) {
                            float* d = acc[mt][nh * 4 + j];
                            mma16816(d, ahi[mt], bhi[j]);
                            mma16816(d, ahi[mt], blo[j]);
                            mma16816(d, alo[mt], bhi[j]);
                        }
                }
            }
            __syncthreads();
        }
    }

    // epilogue
#pragma unroll
    for (int mt = 0; mt < 2; mt++) {
        int gr0 = row0 + warp_m * 32 + mt * 16 + g;
        int gr1 = gr0 + 8;
        if (mode == 0) {
            float dv0 = (gr0 < n) ? g_dinv[gr0] : 0.f;
            float dv1 = (gr1 < n) ? g_dinv[gr1] : 0.f;
#pragma unroll
            for (int nt = 0; nt < 8; nt++) {
                int col = warp_n * 64 + nt * 8 + 2 * t4;
                if (gr0 < n) {
                    float2 v = make_float2(acc[mt][nt][0] * dv0, acc[mt][nt][1] * dv0);
                    *(float2*)&g_hw[(size_t)gr0 * DD + col] = v;
                }
                if (gr1 < n) {
                    float2 v = make_float2(acc[mt][nt][2] * dv1, acc[mt][nt][3] * dv1);
                    *(float2*)&g_hw[(size_t)gr1 * DD + col] = v;
                }
            }
        } else {
#pragma unroll
            for (int nt = 0; nt < 8; nt++) {
                int col = warp_n * 64 + nt * 8 + 2 * t4;
                float2 bb = *(const float2*)&lb[col];
                if (gr0 < n) {
                    float2 v = make_float2(acc[mt][nt][0] + bb.x, acc[mt][nt][1] + bb.y);
                    *(float2*)&outp[(size_t)gr0 * DD + col] = v;
                }
                if (gr1 < n) {
                    float2 v = make_float2(acc[mt][nt][2] + bb.x, acc[mt][nt][3] + bb.y);
                    *(float2*)&outp[(size_t)gr1 * DD + col] = v;
                }
            }
        }
    }
}

// ------- fused aggregate + bias + ELU + residual: one warp per dst node -------
__global__ void aggregate_kernel(const float* __restrict__ x,
                                 const float* __restrict__ conv_b,
                                 int layer, int n)
{
    int w = (blockIdx.x * blockDim.x + threadIdx.x) >> 5;
    if (w >= n) return;
    int lane = threadIdx.x & 31;

    const float* hin = sel_in(layer, x);
    float* hout = sel_out(layer);
    const float* b = conv_b + (size_t)layer * DD;
    const float4* hw4 = (const float4*)g_hw;

    float4 a0 = hw4[(size_t)w * 32 + lane];   // self-loop (pre-scaled by dinv[w])
    float4 a1 = make_float4(0.f, 0.f, 0.f, 0.f);

    int j   = g_off[w];
    int end = j + g_cnt[w];
    for (; j + 2 <= end; j += 2) {
        int s0 = g_csr[j], s1 = g_csr[j + 1];
        float4 v0 = hw4[(size_t)s0 * 32 + lane];
        float4 v1 = hw4[(size_t)s1 * 32 + lane];
        a0.x += v0.x; a0.y += v0.y; a0.z += v0.z; a0.w += v0.w;
        a1.x += v1.x; a1.y += v1.y; a1.z += v1.z; a1.w += v1.w;
    }
    if (j < end) {
        int s0 = g_csr[j];
        float4 v0 = hw4[(size_t)s0 * 32 + lane];
        a0.x += v0.x; a0.y += v0.y; a0.z += v0.z; a0.w += v0.w;
    }

    float dv = g_dinv[w];
    float4 bb = ((const float4*)b)[lane];
    float4 hi = ((const float4*)hin)[(size_t)w * 32 + lane];
    float4 o;
    float x0 = (a0.x + a1.x) * dv + bb.x; o.x = (x0 > 0.f ? x0 : expm1f(x0)) + hi.x;
    float x1 = (a0.y + a1.y) * dv + bb.y; o.y = (x1 > 0.f ? x1 : expm1f(x1)) + hi.y;
    float x2 = (a0.z + a1.z) * dv + bb.z; o.z = (x2 > 0.f ? x2 : expm1f(x2)) + hi.z;
    float x3 = (a0.w + a1.w) * dv + bb.w; o.w = (x3 > 0.f ? x3 : expm1f(x3)) + hi.w;
    ((float4*)hout)[(size_t)w * 32 + lane] = o;
}

// ---------------- launch ----------------
extern "C" void kernel_launch(void* const* d_in, const int* in_sizes, int n_in,
                              void* d_out, int out_size)
{
    const float* x      = (const float*)d_in[0];
    const void*  ei     = d_in[1];
    const float* conv_w = (const float*)d_in[2];       // [3,128,128]
    const float* conv_b = (const float*)d_in[3];       // [3,128]
    const float* lin_w  = (const float*)d_in[4];       // [128,512]
    const float* lin_b  = (const float*)d_in[5];       // [128]
    float*       out    = (float*)d_out;

    int n = in_sizes[0] / DD;       // 100000
    int e = in_sizes[1] / 2;        // 1600000

    int nb_n  = (n + 255) / 256;
    int nb_e  = (e + 255) / 256;
    int npart = (n + 255) / 256;    // <= NPARTMAX

    detect_kernel      <<<1, 32>>>(ei, n);
    zero_kernel        <<<nb_n, 256>>>(n);
    convert_hist_kernel<<<nb_e, 256>>>(ei, e, n);
    scan1_kernel       <<<npart, 256>>>(n);
    scan2_kernel       <<<1, NPARTMAX>>>(npart);
    scan3_kernel       <<<nb_n, 256>>>(n);
    fill_kernel        <<<nb_e, 256>>>(e);

    int gblocks    = (n + 127) / 128;
    int agg_blocks = (n * 32 + 255) / 256;

    for (int l = 0; l < 3; l++) {
        gemm_tc_kernel<<<gblocks, 256>>>(x, conv_w + (size_t)l * DD * DD,
                                         nullptr, nullptr, l, 0, n);
        aggregate_kernel<<<agg_blocks, 256>>>(x, conv_b, l, n);
    }

    gemm_tc_kernel<<<gblocks, 256>>>(x, lin_w, lin_b, out, 0, 1, n);
}

// round 6
// speedup vs baseline: 2.0721x; 1.0501x over previous
#include <cuda_runtime.h>
#include <cuda_bf16.h>
#include <cuda_fp16.h>
#include <math.h>

#define DD 128
#define MAXN 100000
#define MAXE 1600000
#define NPARTMAX 512

// ---------------- scratch (device globals) ----------------
__device__ int    g_is64;
__device__ int    g_src [MAXE];
__device__ int    g_dst [MAXE];
__device__ float  g_dinv[MAXN];
__device__ int    g_cnt [MAXN];
__device__ int    g_off [MAXN];
__device__ int    g_cur [MAXN];
__device__ int    g_csr [MAXE];
__device__ int    g_part[NPARTMAX];
__device__ __half g_hwh[ (size_t)MAXN * DD ];   // fp16 pre-aggregation intermediate
__device__ float  g_h0 [ (size_t)MAXN * DD ];
__device__ float  g_h1 [ (size_t)MAXN * DD ];
__device__ float  g_h2 [ (size_t)MAXN * DD ];

__device__ __forceinline__ const float* sel_in(int sel, const float* x) {
    return sel == 0 ? x : (sel == 1 ? g_h0 : (sel == 2 ? g_h1 : g_h2));
}
__device__ __forceinline__ float* sel_out(int sel) {
    return sel == 0 ? g_h0 : (sel == 1 ? g_h1 : g_h2);
}

// ---------------- edge dtype detect + normalize (+histogram fused) ----------------
__global__ void detect_kernel(const void* ei, int n) {
    if (threadIdx.x == 0 && blockIdx.x == 0) {
        const long long* e64 = (const long long*)ei;
        int is64 = 1;
        for (int i = 0; i < 64; i++) {
            long long v = e64[i];
            if (v < 0 || v >= (long long)n) { is64 = 0; break; }
        }
        g_is64 = is64;
    }
}

__global__ void zero_kernel(int n) {
    int i = blockIdx.x * blockDim.x + threadIdx.x;
    if (i < n) { g_cnt[i] = 0; g_cur[i] = 0; }
}

__global__ void convert_hist_kernel(const void* ei, int ne, int n) {
    int e = blockIdx.x * blockDim.x + threadIdx.x;
    if (e >= ne) return;
    int s, d;
    if (g_is64) {
        const long long* p = (const long long*)ei;
        s = (int)p[e];
        d = (int)p[(size_t)ne + e];
    } else {
        const int* p = (const int*)ei;
        s = p[e];
        d = p[(size_t)ne + e];
    }
    if ((unsigned)s >= (unsigned)n) s = 0;
    if ((unsigned)d >= (unsigned)n) d = 0;
    g_src[e] = s;
    g_dst[e] = d;
    atomicAdd(&g_cnt[d], 1);
}

// ---------------- CSR scan/fill ----------------
__global__ void scan1_kernel(int n) {
    __shared__ int sh[256];
    int tid = threadIdx.x;
    int i = blockIdx.x * 256 + tid;
    int v = (i < n) ? g_cnt[i] : 0;
    sh[tid] = v;
    __syncthreads();
#pragma unroll
    for (int d = 1; d < 256; d <<= 1) {
        int t = (tid >= d) ? sh[tid - d] : 0;
        __syncthreads();
        sh[tid] += t;
        __syncthreads();
    }
    if (i < n) g_off[i] = sh[tid] - v;
    if (tid == 255) g_part[blockIdx.x] = sh[255];
}

__global__ void scan2_kernel(int npart) {
    __shared__ int sh[NPARTMAX];
    int tid = threadIdx.x;
    int v = (tid < npart) ? g_part[tid] : 0;
    sh[tid] = v;
    __syncthreads();
#pragma unroll
    for (int d = 1; d < NPARTMAX; d <<= 1) {
        int t = (tid >= d) ? sh[tid - d] : 0;
        __syncthreads();
        sh[tid] += t;
        __syncthreads();
    }
    if (tid < npart) g_part[tid] = sh[tid] - v;
}

__global__ void scan3_kernel(int n) {
    int i = blockIdx.x * blockDim.x + threadIdx.x;
    if (i < n) {
        g_off[i] += g_part[i >> 8];
        g_dinv[i] = rsqrtf((float)(g_cnt[i] + 1));
    }
}

__global__ void fill_kernel(int ne) {
    int e = blockIdx.x * blockDim.x + threadIdx.x;
    if (e < ne) {
        int d = g_dst[e];
        int p = g_off[d] + atomicAdd(&g_cur[d], 1);
        g_csr[p] = g_src[e];
    }
}

// ---------------- bf16 hi/lo helpers ----------------
__device__ __forceinline__ uint2 cvt_pair(float a, float b) {
    __nv_bfloat16 ha = __float2bfloat16_rn(a);
    __nv_bfloat16 hb = __float2bfloat16_rn(b);
    float ra = a - __bfloat162float(ha);
    float rb = b - __bfloat162float(hb);
    __nv_bfloat162 hp = __halves2bfloat162(ha, hb);
    __nv_bfloat162 lp = __floats2bfloat162_rn(ra, rb);
    uint2 u;
    u.x = *(const unsigned int*)&hp;
    u.y = *(const unsigned int*)&lp;
    return u;
}

__device__ __forceinline__ void mma16816(float* d, const unsigned* a, const unsigned* b) {
    asm volatile(
        "mma.sync.aligned.m16n8k16.row.col.f32.bf16.bf16.f32 "
        "{%0,%1,%2,%3}, {%4,%5,%6,%7}, {%8,%9}, {%0,%1,%2,%3};\n"
        : "+f"(d[0]), "+f"(d[1]), "+f"(d[2]), "+f"(d[3])
        : "r"(a[0]), "r"(a[1]), "r"(a[2]), "r"(a[3]), "r"(b[0]), "r"(b[1]));
}

// ============== tensor-core GEMM (bf16x3): C[128rows x 128cols] per block ==============
// mode 0: epilogue (C * dinv[row]) -> g_hwh (fp16)   (conv layer)
// mode 1: epilogue (C + lin_b)     -> out  (fp32)    (final layer, 4 sources x 128 K)
__global__ __launch_bounds__(256) void gemm_tc_kernel(
    const float* __restrict__ x,
    const float* __restrict__ wptr,
    const float* __restrict__ lb,
    float* __restrict__ outp,
    int layer, int mode, int n)
{
    __shared__ uint2 sA[128 * 17];
    __shared__ uint2 sW[128 * 17];

    int row0 = blockIdx.x * 128;
    int t    = threadIdx.x;
    int warp = t >> 5;
    int lane = t & 31;
    int g    = lane >> 2;
    int t4   = lane & 3;
    int warp_m = warp & 3;
    int warp_n = warp >> 2;

    float acc[2][8][4];
#pragma unroll
    for (int a = 0; a < 2; a++)
#pragma unroll
        for (int b = 0; b < 8; b++)
#pragma unroll
            for (int c = 0; c < 4; c++) acc[a][b][c] = 0.f;

    int nsrc = (mode == 0) ? 1 : 4;
    int wstride = (mode == 0) ? DD : 512;

    for (int s = 0; s < nsrc; s++) {
        const float* A = (mode == 0) ? sel_in(layer, x) : sel_in(s, x);
        int kbase_src = (mode == 0) ? 0 : s * DD;

        for (int kc = 0; kc < 4; kc++) {
            int kb = kc * 32;
            for (int idx = t; idx < 1024; idx += 256) {
                int r = idx >> 3, q = idx & 7;
                int gr = row0 + r;
                float4 f = make_float4(0.f, 0.f, 0.f, 0.f);
                if (gr < n) f = *(const float4*)&A[(size_t)gr * DD + kb + q * 4];
                sA[r * 17 + q * 2]     = cvt_pair(f.x, f.y);
                sA[r * 17 + q * 2 + 1] = cvt_pair(f.z, f.w);
            }
            for (int idx = t; idx < 1024; idx += 256) {
                int c = idx >> 3, q = idx & 7;
                float4 f = *(const float4*)&wptr[(size_t)c * wstride + kbase_src + kb + q * 4];
                sW[c * 17 + q * 2]     = cvt_pair(f.x, f.y);
                sW[c * 17 + q * 2 + 1] = cvt_pair(f.z, f.w);
            }
            __syncthreads();

#pragma unroll
            for (int kk = 0; kk < 2; kk++) {
                int pb = kk * 8;
                unsigned ahi[2][4], alo[2][4];
#pragma unroll
                for (int mt = 0; mt < 2; mt++) {
                    int r0 = warp_m * 32 + mt * 16 + g;
                    uint2 u0 = sA[r0 * 17 + pb + t4];
                    uint2 u1 = sA[(r0 + 8) * 17 + pb + t4];
                    uint2 u2 = sA[r0 * 17 + pb + t4 + 4];
                    uint2 u3 = sA[(r0 + 8) * 17 + pb + t4 + 4];
                    ahi[mt][0] = u0.x; ahi[mt][1] = u1.x; ahi[mt][2] = u2.x; ahi[mt][3] = u3.x;
                    alo[mt][0] = u0.y; alo[mt][1] = u1.y; alo[mt][2] = u2.y; alo[mt][3] = u3.y;
                }
#pragma unroll
                for (int nh = 0; nh < 2; nh++) {
                    unsigned bhi[4][2], blo[4][2];
#pragma unroll
                    for (int j = 0; j < 4; j++) {
                        int c = warp_n * 64 + (nh * 4 + j) * 8 + g;
                        uint2 v0 = sW[c * 17 + pb + t4];
                        uint2 v1 = sW[c * 17 + pb + t4 + 4];
                        bhi[j][0] = v0.x; bhi[j][1] = v1.x;
                        blo[j][0] = v0.y; blo[j][1] = v1.y;
                    }
#pragma unroll
                    for (int mt = 0; mt < 2; mt++)
#pragma unroll
                        for (int j = 0; j < 4; j++) {
                            float* d = acc[mt][nh * 4 + j];
                            mma16816(d, ahi[mt], bhi[j]);
                            mma16816(d, ahi[mt], blo[j]);
                            mma16816(d, alo[mt], bhi[j]);
                        }
                }
            }
            __syncthreads();
        }
    }

    // epilogue
#pragma unroll
    for (int mt = 0; mt < 2; mt++) {
        int gr0 = row0 + warp_m * 32 + mt * 16 + g;
        int gr1 = gr0 + 8;
        if (mode == 0) {
            float dv0 = (gr0 < n) ? g_dinv[gr0] : 0.f;
            float dv1 = (gr1 < n) ? g_dinv[gr1] : 0.f;
#pragma unroll
            for (int nt = 0; nt < 8; nt++) {
                int col = warp_n * 64 + nt * 8 + 2 * t4;
                if (gr0 < n)
                    *(__half2*)&g_hwh[(size_t)gr0 * DD + col] =
                        __floats2half2_rn(acc[mt][nt][0] * dv0, acc[mt][nt][1] * dv0);
                if (gr1 < n)
                    *(__half2*)&g_hwh[(size_t)gr1 * DD + col] =
                        __floats2half2_rn(acc[mt][nt][2] * dv1, acc[mt][nt][3] * dv1);
            }
        } else {
#pragma unroll
            for (int nt = 0; nt < 8; nt++) {
                int col = warp_n * 64 + nt * 8 + 2 * t4;
                float2 bb = *(const float2*)&lb[col];
                if (gr0 < n) {
                    float2 v = make_float2(acc[mt][nt][0] + bb.x, acc[mt][nt][1] + bb.y);
                    *(float2*)&outp[(size_t)gr0 * DD + col] = v;
                }
                if (gr1 < n) {
                    float2 v = make_float2(acc[mt][nt][2] + bb.x, acc[mt][nt][3] + bb.y);
                    *(float2*)&outp[(size_t)gr1 * DD + col] = v;
                }
            }
        }
    }
}

// ---------------- fp16 row gather helper: 4 halves per lane ----------------
__device__ __forceinline__ float4 ld_hw4(int row, int lane) {
    uint2 u = ((const uint2*)g_hwh)[(size_t)row * 32 + lane];
    float2 f0 = __half22float2(*(const __half2*)&u.x);
    float2 f1 = __half22float2(*(const __half2*)&u.y);
    return make_float4(f0.x, f0.y, f1.x, f1.y);
}

// ------- fused aggregate + bias + ELU + residual: one warp per dst node -------
__global__ void aggregate_kernel(const float* __restrict__ x,
                                 const float* __restrict__ conv_b,
                                 int layer, int n)
{
    int w = (blockIdx.x * blockDim.x + threadIdx.x) >> 5;
    if (w >= n) return;
    int lane = threadIdx.x & 31;

    const float* hin = sel_in(layer, x);
    float* hout = sel_out(layer);
    const float* b = conv_b + (size_t)layer * DD;

    float4 a0 = ld_hw4(w, lane);   // self-loop (pre-scaled by dinv[w])
    float4 a1 = make_float4(0.f, 0.f, 0.f, 0.f);
    float4 a2 = make_float4(0.f, 0.f, 0.f, 0.f);
    float4 a3 = make_float4(0.f, 0.f, 0.f, 0.f);

    int j   = g_off[w];
    int end = j + g_cnt[w];
    for (; j + 4 <= end; j += 4) {
        int s0 = g_csr[j], s1 = g_csr[j + 1], s2 = g_csr[j + 2], s3 = g_csr[j + 3];
        float4 v0 = ld_hw4(s0, lane);
        float4 v1 = ld_hw4(s1, lane);
        float4 v2 = ld_hw4(s2, lane);
        float4 v3 = ld_hw4(s3, lane);
        a0.x += v0.x; a0.y += v0.y; a0.z += v0.z; a0.w += v0.w;
        a1.x += v1.x; a1.y += v1.y; a1.z += v1.z; a1.w += v1.w;
        a2.x += v2.x; a2.y += v2.y; a2.z += v2.z; a2.w += v2.w;
        a3.x += v3.x; a3.y += v3.y; a3.z += v3.z; a3.w += v3.w;
    }
    for (; j < end; j++) {
        float4 v0 = ld_hw4(g_csr[j], lane);
        a0.x += v0.x; a0.y += v0.y; a0.z += v0.z; a0.w += v0.w;
    }

    float dv = g_dinv[w];
    float4 bb = ((const float4*)b)[lane];
    float4 hi = ((const float4*)hin)[(size_t)w * 32 + lane];
    float4 o;
    float x0 = (a0.x + a1.x + a2.x + a3.x) * dv + bb.x; o.x = (x0 > 0.f ? x0 : expm1f(x0)) + hi.x;
    float x1 = (a0.y + a1.y + a2.y + a3.y) * dv + bb.y; o.y = (x1 > 0.f ? x1 : expm1f(x1)) + hi.y;
    float x2 = (a0.z + a1.z + a2.z + a3.z) * dv + bb.z; o.z = (x2 > 0.f ? x2 : expm1f(x2)) + hi.z;
    float x3 = (a0.w + a1.w + a2.w + a3.w) * dv + bb.w; o.w = (x3 > 0.f ? x3 : expm1f(x3)) + hi.w;
    ((float4*)hout)[(size_t)w * 32 + lane] = o;
}

// ---------------- launch ----------------
extern "C" void kernel_launch(void* const* d_in, const int* in_sizes, int n_in,
                              void* d_out, int out_size)
{
    const float* x      = (const float*)d_in[0];
    const void*  ei     = d_in[1];
    const float* conv_w = (const float*)d_in[2];       // [3,128,128]
    const float* conv_b = (const float*)d_in[3];       // [3,128]
    const float* lin_w  = (const float*)d_in[4];       // [128,512]
    const float* lin_b  = (const float*)d_in[5];       // [128]
    float*       out    = (float*)d_out;

    int n = in_sizes[0] / DD;       // 100000
    int e = in_sizes[1] / 2;        // 1600000

    int nb_n  = (n + 255) / 256;
    int nb_e  = (e + 255) / 256;
    int npart = (n + 255) / 256;    // <= NPARTMAX

    detect_kernel      <<<1, 32>>>(ei, n);
    zero_kernel        <<<nb_n, 256>>>(n);
    convert_hist_kernel<<<nb_e, 256>>>(ei, e, n);
    scan1_kernel       <<<npart, 256>>>(n);
    scan2_kernel       <<<1, NPARTMAX>>>(npart);
    scan3_kernel       <<<nb_n, 256>>>(n);
    fill_kernel        <<<nb_e, 256>>>(e);

    int gblocks    = (n + 127) / 128;
    int agg_blocks = (n * 32 + 255) / 256;

    for (int l = 0; l < 3; l++) {
        gemm_tc_kernel<<<gblocks, 256>>>(x, conv_w + (size_t)l * DD * DD,
                                         nullptr, nullptr, l, 0, n);
        aggregate_kernel<<<agg_blocks, 256>>>(x, conv_b, l, n);
    }

    gemm_tc_kernel<<<gblocks, 256>>>(x, lin_w, lin_b, out, 0, 1, n);
}

// round 7
// speedup vs baseline: 2.3997x; 1.1581x over previous
#include <cuda_runtime.h>
#include <cuda_bf16.h>
#include <cuda_fp16.h>
#include <math.h>

#define DD 128
#define MAXN 100000
#define MAXE 1600000
#define NPARTMAX 512
#define SPAD 18   // smem row stride in uint2 (16B-aligned vec copies)

// ---------------- scratch (device globals) ----------------
__device__ int    g_is64;
__device__ int    g_src [MAXE];
__device__ int    g_dst [MAXE];
__device__ float  g_dinv[MAXN];
__device__ int    g_cnt [MAXN];
__device__ int    g_off [MAXN];
__device__ int    g_cur [MAXN];
__device__ int    g_csr [MAXE];
__device__ int    g_part[NPARTMAX];
__device__ __half g_hwh[ (size_t)MAXN * DD ];      // fp16 pre-aggregation intermediate
// hi/lo bf16 pair storage: uint2 q covers elements (2q, 2q+1): x=hi pair, y=lo pair
__device__ uint2  g_xb [ (size_t)MAXN * 64 ];
__device__ uint2  g_hb0[ (size_t)MAXN * 64 ];
__device__ uint2  g_hb1[ (size_t)MAXN * 64 ];
__device__ uint2  g_hb2[ (size_t)MAXN * 64 ];
// converted weights: conv (3 * 128 rows * 64 pairs) then lin (128 rows * 256 pairs)
#define WB_LIN_OFF (3 * 128 * 64)
__device__ uint2  g_wb [ WB_LIN_OFF + 128 * 256 ];

__device__ __forceinline__ const uint2* sel_hb(int sel) {
    return sel == 0 ? g_xb : (sel == 1 ? g_hb0 : (sel == 2 ? g_hb1 : g_hb2));
}
__device__ __forceinline__ uint2* sel_hb_out(int sel) {
    return sel == 0 ? g_hb0 : (sel == 1 ? g_hb1 : g_hb2);
}

// ---------------- bf16 hi/lo helpers ----------------
__device__ __forceinline__ uint2 cvt_pair(float a, float b) {
    __nv_bfloat16 ha = __float2bfloat16_rn(a);
    __nv_bfloat16 hb = __float2bfloat16_rn(b);
    float ra = a - __bfloat162float(ha);
    float rb = b - __bfloat162float(hb);
    __nv_bfloat162 hp = __halves2bfloat162(ha, hb);
    __nv_bfloat162 lp = __floats2bfloat162_rn(ra, rb);
    uint2 u;
    u.x = *(const unsigned int*)&hp;
    u.y = *(const unsigned int*)&lp;
    return u;
}

__device__ __forceinline__ float2 rec_pair(uint2 u) {
    float2 h = __bfloat1622float2(*(const __nv_bfloat162*)&u.x);
    float2 l = __bfloat1622float2(*(const __nv_bfloat162*)&u.y);
    return make_float2(h.x + l.x, h.y + l.y);
}

// ---------------- edge dtype detect ----------------
__global__ void detect_kernel(const void* ei, int n) {
    if (threadIdx.x == 0 && blockIdx.x == 0) {
        const long long* e64 = (const long long*)ei;
        int is64 = 1;
        for (int i = 0; i < 64; i++) {
            long long v = e64[i];
            if (v < 0 || v >= (long long)n) { is64 = 0; break; }
        }
        g_is64 = is64;
    }
}

// ---------------- prep: convert x and weights to hi/lo ----------------
__global__ void prep_x_kernel(const float* __restrict__ x, int n) {
    int i = blockIdx.x * blockDim.x + threadIdx.x;   // over n*32 float4s
    if (i >= n * 32) return;
    float4 f = ((const float4*)x)[i];
    g_xb[2 * i]     = cvt_pair(f.x, f.y);
    g_xb[2 * i + 1] = cvt_pair(f.z, f.w);
}

__global__ void prep_w_kernel(const float* __restrict__ conv_w,
                              const float* __restrict__ lin_w) {
    int i = blockIdx.x * blockDim.x + threadIdx.x;
    // conv: 3*128*128 = 49152 floats = 12288 float4
    if (i < 12288) {
        float4 f = ((const float4*)conv_w)[i];
        g_wb[2 * i]     = cvt_pair(f.x, f.y);
        g_wb[2 * i + 1] = cvt_pair(f.z, f.w);
    }
    // lin: 128*512 = 65536 floats = 16384 float4
    if (i < 16384) {
        float4 f = ((const float4*)lin_w)[i];
        g_wb[WB_LIN_OFF + 2 * i]     = cvt_pair(f.x, f.y);
        g_wb[WB_LIN_OFF + 2 * i + 1] = cvt_pair(f.z, f.w);
    }
}

// ---------------- CSR build ----------------
__global__ void zero_kernel(int n) {
    int i = blockIdx.x * blockDim.x + threadIdx.x;
    if (i < n) { g_cnt[i] = 0; g_cur[i] = 0; }
}

__global__ void convert_hist_kernel(const void* ei, int ne, int n) {
    int e = blockIdx.x * blockDim.x + threadIdx.x;
    if (e >= ne) return;
    int s, d;
    if (g_is64) {
        const long long* p = (const long long*)ei;
        s = (int)p[e];
        d = (int)p[(size_t)ne + e];
    } else {
        const int* p = (const int*)ei;
        s = p[e];
        d = p[(size_t)ne + e];
    }
    if ((unsigned)s >= (unsigned)n) s = 0;
    if ((unsigned)d >= (unsigned)n) d = 0;
    g_src[e] = s;
    g_dst[e] = d;
    atomicAdd(&g_cnt[d], 1);
}

__global__ void scan1_kernel(int n) {
    __shared__ int sh[256];
    int tid = threadIdx.x;
    int i = blockIdx.x * 256 + tid;
    int v = (i < n) ? g_cnt[i] : 0;
    sh[tid] = v;
    __syncthreads();
#pragma unroll
    for (int d = 1; d < 256; d <<= 1) {
        int t = (tid >= d) ? sh[tid - d] : 0;
        __syncthreads();
        sh[tid] += t;
        __syncthreads();
    }
    if (i < n) g_off[i] = sh[tid] - v;
    if (tid == 255) g_part[blockIdx.x] = sh[255];
}

__global__ void scan2_kernel(int npart) {
    __shared__ int sh[NPARTMAX];
    int tid = threadIdx.x;
    int v = (tid < npart) ? g_part[tid] : 0;
    sh[tid] = v;
    __syncthreads();
#pragma unroll
    for (int d = 1; d < NPARTMAX; d <<= 1) {
        int t = (tid >= d) ? sh[tid - d] : 0;
        __syncthreads();
        sh[tid] += t;
        __syncthreads();
    }
    if (tid < npart) g_part[tid] = sh[tid] - v;
}

__global__ void scan3_kernel(int n) {
    int i = blockIdx.x * blockDim.x + threadIdx.x;
    if (i < n) {
        g_off[i] += g_part[i >> 8];
        g_dinv[i] = rsqrtf((float)(g_cnt[i] + 1));
    }
}

__global__ void fill_kernel(int ne) {
    int e = blockIdx.x * blockDim.x + threadIdx.x;
    if (e < ne) {
        int d = g_dst[e];
        int p = g_off[d] + atomicAdd(&g_cur[d], 1);
        g_csr[p] = g_src[e];
    }
}

__device__ __forceinline__ void mma16816(float* d, const unsigned* a, const unsigned* b) {
    asm volatile(
        "mma.sync.aligned.m16n8k16.row.col.f32.bf16.bf16.f32 "
        "{%0,%1,%2,%3}, {%4,%5,%6,%7}, {%8,%9}, {%0,%1,%2,%3};\n"
        : "+f"(d[0]), "+f"(d[1]), "+f"(d[2]), "+f"(d[3])
        : "r"(a[0]), "r"(a[1]), "r"(a[2]), "r"(a[3]), "r"(b[0]), "r"(b[1]));
}

// ============== tensor-core GEMM (bf16x3), pure-copy loaders ==============
// mode 0: C = A @ Wl^T, epilogue *dinv[row] -> g_hwh (fp16)
// mode 1: C = concat(x,h0,h1,h2) @ lin_w^T + lin_b -> out (fp32)
__global__ __launch_bounds__(256) void gemm_tc_kernel(
    const float* __restrict__ lb,
    float* __restrict__ outp,
    int layer, int mode, int n)
{
    __shared__ uint2 sA[128 * SPAD];
    __shared__ uint2 sW[128 * SPAD];

    int row0 = blockIdx.x * 128;
    int t    = threadIdx.x;
    int warp = t >> 5;
    int lane = t & 31;
    int g    = lane >> 2;
    int t4   = lane & 3;
    int warp_m = warp & 3;
    int warp_n = warp >> 2;

    float acc[2][8][4];
#pragma unroll
    for (int a = 0; a < 2; a++)
#pragma unroll
        for (int b = 0; b < 8; b++)
#pragma unroll
            for (int c = 0; c < 4; c++) acc[a][b][c] = 0.f;

    int nsrc = (mode == 0) ? 1 : 4;
    int wstride2 = (mode == 0) ? 64 : 256;   // uint2 pairs per weight row
    const uint2* wb = (mode == 0) ? (g_wb + (size_t)layer * 128 * 64)
                                  : (g_wb + WB_LIN_OFF);

    for (int s = 0; s < nsrc; s++) {
        const uint2* Ab = (mode == 0) ? sel_hb(layer) : sel_hb(s);
        int kw2 = s * 64;   // pair offset into weight row for this source

        for (int kc = 0; kc < 4; kc++) {
            int k2 = kc * 16;   // pair offset within A row
            // A chunk copy: 128 rows x 16 pairs, vectorized 2 pairs/iter
            for (int idx = t; idx < 1024; idx += 256) {
                int r = idx >> 3, j = idx & 7;
                int gr = row0 + r;
                uint4 v = make_uint4(0u, 0u, 0u, 0u);
                if (gr < n) v = *(const uint4*)&Ab[(size_t)gr * 64 + k2 + 2 * j];
                *(uint4*)&sA[r * SPAD + 2 * j] = v;
            }
            // W chunk copy
            for (int idx = t; idx < 1024; idx += 256) {
                int c = idx >> 3, j = idx & 7;
                uint4 v = *(const uint4*)&wb[(size_t)c * wstride2 + kw2 + k2 + 2 * j];
                *(uint4*)&sW[c * SPAD + 2 * j] = v;
            }
            __syncthreads();

#pragma unroll
            for (int kk = 0; kk < 2; kk++) {
                int pb = kk * 8;
                unsigned ahi[2][4], alo[2][4];
#pragma unroll
                for (int mt = 0; mt < 2; mt++) {
                    int r0 = warp_m * 32 + mt * 16 + g;
                    uint2 u0 = sA[r0 * SPAD + pb + t4];
                    uint2 u1 = sA[(r0 + 8) * SPAD + pb + t4];
                    uint2 u2 = sA[r0 * SPAD + pb + t4 + 4];
                    uint2 u3 = sA[(r0 + 8) * SPAD + pb + t4 + 4];
                    ahi[mt][0] = u0.x; ahi[mt][1] = u1.x; ahi[mt][2] = u2.x; ahi[mt][3] = u3.x;
                    alo[mt][0] = u0.y; alo[mt][1] = u1.y; alo[mt][2] = u2.y; alo[mt][3] = u3.y;
                }
#pragma unroll
                for (int nh = 0; nh < 2; nh++) {
                    unsigned bhi[4][2], blo[4][2];
#pragma unroll
                    for (int j = 0; j < 4; j++) {
                        int c = warp_n * 64 + (nh * 4 + j) * 8 + g;
                        uint2 v0 = sW[c * SPAD + pb + t4];
                        uint2 v1 = sW[c * SPAD + pb + t4 + 4];
                        bhi[j][0] = v0.x; bhi[j][1] = v1.x;
                        blo[j][0] = v0.y; blo[j][1] = v1.y;
                    }
#pragma unroll
                    for (int mt = 0; mt < 2; mt++)
#pragma unroll
                        for (int j = 0; j < 4; j++) {
                            float* d = acc[mt][nh * 4 + j];
                            mma16816(d, ahi[mt], bhi[j]);
                            mma16816(d, ahi[mt], blo[j]);
                            mma16816(d, alo[mt], bhi[j]);
                        }
                }
            }
            __syncthreads();
        }
    }

    // epilogue
#pragma unroll
    for (int mt = 0; mt < 2; mt++) {
        int gr0 = row0 + warp_m * 32 + mt * 16 + g;
        int gr1 = gr0 + 8;
        if (mode == 0) {
            float dv0 = (gr0 < n) ? g_dinv[gr0] : 0.f;
            float dv1 = (gr1 < n) ? g_dinv[gr1] : 0.f;
#pragma unroll
            for (int nt = 0; nt < 8; nt++) {
                int col = warp_n * 64 + nt * 8 + 2 * t4;
                if (gr0 < n)
                    *(__half2*)&g_hwh[(size_t)gr0 * DD + col] =
                        __floats2half2_rn(acc[mt][nt][0] * dv0, acc[mt][nt][1] * dv0);
                if (gr1 < n)
                    *(__half2*)&g_hwh[(size_t)gr1 * DD + col] =
                        __floats2half2_rn(acc[mt][nt][2] * dv1, acc[mt][nt][3] * dv1);
            }
        } else {
#pragma unroll
            for (int nt = 0; nt < 8; nt++) {
                int col = warp_n * 64 + nt * 8 + 2 * t4;
                float2 bb = *(const float2*)&lb[col];
                if (gr0 < n) {
                    float2 v = make_float2(acc[mt][nt][0] + bb.x, acc[mt][nt][1] + bb.y);
                    *(float2*)&outp[(size_t)gr0 * DD + col] = v;
                }
                if (gr1 < n) {
                    float2 v = make_float2(acc[mt][nt][2] + bb.x, acc[mt][nt][3] + bb.y);
                    *(float2*)&outp[(size_t)gr1 * DD + col] = v;
                }
            }
        }
    }
}

// ---------------- fp16 row gather: 4 halves per lane ----------------
__device__ __forceinline__ float4 ld_hw4(int row, int lane) {
    uint2 u = ((const uint2*)g_hwh)[(size_t)row * 32 + lane];
    float2 f0 = __half22float2(*(const __half2*)&u.x);
    float2 f1 = __half22float2(*(const __half2*)&u.y);
    return make_float4(f0.x, f0.y, f1.x, f1.y);
}

// ------- fused aggregate + bias + ELU + residual; hi/lo output -------
__global__ void aggregate_kernel(const float* __restrict__ conv_b,
                                 int layer, int n)
{
    int w = (blockIdx.x * blockDim.x + threadIdx.x) >> 5;
    if (w >= n) return;
    int lane = threadIdx.x & 31;

    const uint2* hb_in = sel_hb(layer);
    uint2* hb_out = sel_hb_out(layer);
    const float* b = conv_b + (size_t)layer * DD;

    float4 a0 = ld_hw4(w, lane);   // self-loop (pre-scaled by dinv[w])
    float4 a1 = make_float4(0.f, 0.f, 0.f, 0.f);
    float4 a2 = make_float4(0.f, 0.f, 0.f, 0.f);
    float4 a3 = make_float4(0.f, 0.f, 0.f, 0.f);

    int j   = g_off[w];
    int end = j + g_cnt[w];
    for (; j + 4 <= end; j += 4) {
        int s0 = g_csr[j], s1 = g_csr[j + 1], s2 = g_csr[j + 2], s3 = g_csr[j + 3];
        float4 v0 = ld_hw4(s0, lane);
        float4 v1 = ld_hw4(s1, lane);
        float4 v2 = ld_hw4(s2, lane);
        float4 v3 = ld_hw4(s3, lane);
        a0.x += v0.x; a0.y += v0.y; a0.z += v0.z; a0.w += v0.w;
        a1.x += v1.x; a1.y += v1.y; a1.z += v1.z; a1.w += v1.w;
        a2.x += v2.x; a2.y += v2.y; a2.z += v2.z; a2.w += v2.w;
        a3.x += v3.x; a3.y += v3.y; a3.z += v3.z; a3.w += v3.w;
    }
    for (; j < end; j++) {
        float4 v0 = ld_hw4(g_csr[j], lane);
        a0.x += v0.x; a0.y += v0.y; a0.z += v0.z; a0.w += v0.w;
    }

    float dv = g_dinv[w];
    float4 bb = ((const float4*)b)[lane];
    uint4 hraw = *(const uint4*)&hb_in[(size_t)w * 64 + 2 * lane];
    float2 h01 = rec_pair(make_uint2(hraw.x, hraw.y));
    float2 h23 = rec_pair(make_uint2(hraw.z, hraw.w));

    float4 o;
    float x0 = (a0.x + a1.x + a2.x + a3.x) * dv + bb.x; o.x = (x0 > 0.f ? x0 : expm1f(x0)) + h01.x;
    float x1 = (a0.y + a1.y + a2.y + a3.y) * dv + bb.y; o.y = (x1 > 0.f ? x1 : expm1f(x1)) + h01.y;
    float x2 = (a0.z + a1.z + a2.z + a3.z) * dv + bb.z; o.z = (x2 > 0.f ? x2 : expm1f(x2)) + h23.x;
    float x3 = (a0.w + a1.w + a2.w + a3.w) * dv + bb.w; o.w = (x3 > 0.f ? x3 : expm1f(x3)) + h23.y;

    uint2 p0 = cvt_pair(o.x, o.y);
    uint2 p1 = cvt_pair(o.z, o.w);
    *(uint4*)&hb_out[(size_t)w * 64 + 2 * lane] = make_uint4(p0.x, p0.y, p1.x, p1.y);
}

// ---------------- launch ----------------
extern "C" void kernel_launch(void* const* d_in, const int* in_sizes, int n_in,
                              void* d_out, int out_size)
{
    const float* x      = (const float*)d_in[0];
    const void*  ei     = d_in[1];
    const float* conv_w = (const float*)d_in[2];       // [3,128,128]
    const float* conv_b = (const float*)d_in[3];       // [3,128]
    const float* lin_w  = (const float*)d_in[4];       // [128,512]
    const float* lin_b  = (const float*)d_in[5];       // [128]
    float*       out    = (float*)d_out;

    int n = in_sizes[0] / DD;       // 100000
    int e = in_sizes[1] / 2;        // 1600000

    int nb_n  = (n + 255) / 256;
    int nb_e  = (e + 255) / 256;
    int npart = (n + 255) / 256;    // <= NPARTMAX

    detect_kernel      <<<1, 32>>>(ei, n);
    prep_x_kernel      <<<(n * 32 + 255) / 256, 256>>>(x, n);
    prep_w_kernel      <<<(16384 + 255) / 256, 256>>>(conv_w, lin_w);
    zero_kernel        <<<nb_n, 256>>>(n);
    convert_hist_kernel<<<nb_e, 256>>>(ei, e, n);
    scan1_kernel       <<<npart, 256>>>(n);
    scan2_kernel       <<<1, NPARTMAX>>>(npart);
    scan3_kernel       <<<nb_n, 256>>>(n);
    fill_kernel        <<<nb_e, 256>>>(e);

    int gblocks    = (n + 127) / 128;
    int agg_blocks = (n * 32 + 255) / 256;

    for (int l = 0; l < 3; l++) {
        gemm_tc_kernel<<<gblocks, 256>>>(nullptr, nullptr, l, 0, n);
        aggregate_kernel<<<agg_blocks, 256>>>(conv_b, l, n);
    }

    gemm_tc_kernel<<<gblocks, 256>>>(lin_b, out, 0, 1, n);
}